// round 13
// baseline (speedup 1.0000x reference)
#include <cuda_runtime.h>
#include <cuda_bf16.h>
#include <cstdint>

#define NEG_INF_F 1000000000000.0f
#define W_SCALE 16.0f
#define INV_W_SCALE 0.0625f

// ---------------- scratch (fp8 e4m3) ----------------
__device__ uint8_t g_X8[8192 * 768];    // X e4m3 [m][k]
__device__ uint8_t g_Wt8[1152 * 768];   // (16*W)^T e4m3 [n][k]
__device__ uint8_t g_q8[144 * 512 * 64];
__device__ uint8_t g_k8[144 * 512 * 64];

// ---------------- PTX helpers ----------------
__device__ __forceinline__ uint32_t smem_u32(const void* p) {
    return (uint32_t)__cvta_generic_to_shared(p);
}
__device__ __forceinline__ void ldm_x4(uint32_t* r, uint32_t a) {
    asm volatile("ldmatrix.sync.aligned.m8n8.x4.shared.b16 {%0,%1,%2,%3}, [%4];"
                 : "=r"(r[0]), "=r"(r[1]), "=r"(r[2]), "=r"(r[3]) : "r"(a));
}
__device__ __forceinline__ void mma_fp8(float* c, const uint32_t* a, const uint32_t* b) {
    asm volatile(
        "mma.sync.aligned.m16n8k32.row.col.f32.e4m3.e4m3.f32 "
        "{%0,%1,%2,%3}, {%4,%5,%6,%7}, {%8,%9}, {%0,%1,%2,%3};"
        : "+f"(c[0]), "+f"(c[1]), "+f"(c[2]), "+f"(c[3])
        : "r"(a[0]), "r"(a[1]), "r"(a[2]), "r"(a[3]), "r"(b[0]), "r"(b[1]));
}
__device__ __forceinline__ uint16_t pack_e4m3x2(float hi, float lo) {
    uint16_t r;
    asm("cvt.rn.satfinite.e4m3x2.f32 %0, %1, %2;" : "=h"(r) : "f"(hi), "f"(lo));
    return r;
}
#define CP_ASYNC16(dst, src) \
    asm volatile("cp.async.cg.shared.global [%0], [%1], 16;" :: "r"(dst), "l"(src))
#define CP_COMMIT() asm volatile("cp.async.commit_group;")
#define CP_WAIT(N)  asm volatile("cp.async.wait_group %0;" :: "n"(N))

// ---------------- fused convert kernel ----------------
// blocks [0, 864): W transpose+convert; blocks [864, ...): X convert (2 float4/iter).
__global__ __launch_bounds__(256) void conv_fused_kernel(const float* __restrict__ X,
                                                         const float* __restrict__ W)
{
    if (blockIdx.x < 864) {
        __shared__ float tile[32][33];
        const int bx = blockIdx.x % 36, by = blockIdx.x / 36;
        const int n0 = bx * 32, k0 = by * 32;
        const int tx = threadIdx.x & 31, ty = threadIdx.x >> 5;
        #pragma unroll
        for (int i = 0; i < 4; i++)
            tile[ty + 8 * i][tx] = W[(size_t)(k0 + ty + 8 * i) * 1152 + n0 + tx];
        __syncthreads();
        #pragma unroll
        for (int i = 0; i < 4; i++) {
            const int n = ty + 8 * i;
            float v = tile[tx][n] * W_SCALE;
            uint16_t p = pack_e4m3x2(0.0f, v);
            g_Wt8[(size_t)(n0 + n) * 768 + k0 + tx] = (uint8_t)(p & 0xFF);
        }
    } else {
        const int n4 = 8192 * 768 / 4;           // 1572864 float4s
        const int nb = gridDim.x - 864;
        const int stride = nb * 256;
        for (int i = (blockIdx.x - 864) * 256 + threadIdx.x; i < n4; i += 2 * stride) {
            float4 v0 = ((const float4*)X)[i];
            const int i2 = i + stride;
            float4 v1 = (i2 < n4) ? ((const float4*)X)[i2] : make_float4(0, 0, 0, 0);
            uint16_t lo0 = pack_e4m3x2(v0.y, v0.x), hi0 = pack_e4m3x2(v0.w, v0.z);
            ((uint32_t*)g_X8)[i] = ((uint32_t)hi0 << 16) | lo0;
            if (i2 < n4) {
                uint16_t lo1 = pack_e4m3x2(v1.y, v1.x), hi1 = pack_e4m3x2(v1.w, v1.z);
                ((uint32_t*)g_X8)[i2] = ((uint32_t)hi1 << 16) | lo1;
            }
        }
    }
}

// ---------------- Kernel A: proj GEMM (fp8) + bias + RoPE, staged fp8 output ----------------
// 128x128 tile, 8 warps (2m x 4n), warp tile 64x32. K-tile 128B, double buffer, NT=6.
#define STG_S 192
#define PS 144   // smem row stride (128B data + 16B pad); 36 words -> conflict-free

__global__ __launch_bounds__(256, 2) void proj_mma_kernel(const float* __restrict__ bias)
{
    __shared__ __align__(16) uint8_t As[2][128 * PS];   // reused as output staging
    __shared__ __align__(16) uint8_t Bs[2][128 * PS];
    __shared__ float invf_s[32];

    const int t = threadIdx.x, lane = t & 31, wid = t >> 5;
    const int wm = wid >> 2, wn = wid & 3;
    const int g = lane >> 2, tg = lane & 3;
    const int qd = lane >> 3, rr8 = lane & 7;
    const int m0 = blockIdx.y * 128, n0 = blockIdx.x * 128;

    const int a_r = (qd & 1) * 8 + rr8, a_c = (qd >> 1) * 16;
    const int b_r = (qd >> 1) * 8 + rr8, b_c = (qd & 1) * 16;

    if (t < 32) invf_s[t] = exp2f((float)t * (-13.287712379549449f / 32.0f));

    float c[4][4][4];
    #pragma unroll
    for (int i = 0; i < 4; i++)
        #pragma unroll
        for (int j = 0; j < 4; j++)
            #pragma unroll
            for (int k = 0; k < 4; k++) c[i][j][k] = 0.f;

    const uint32_t sA[2] = {smem_u32(As[0]), smem_u32(As[1])};
    const uint32_t sB[2] = {smem_u32(Bs[0]), smem_u32(Bs[1])};

    // fill one 128B K-tile: A 128x128B (1024 chunks), B same; 8 chunks/thread
    const int ld_row = t >> 1, ld_c = (t & 1) * 64;    // rows 0..127, col offsets 0/64
    auto fill = [&](int buf, int k0) {
        #pragma unroll
        for (int h = 0; h < 2; h++) {
            const int cc = ld_c + h * 16;
            CP_ASYNC16(sA[buf] + ld_row * PS + cc, &g_X8[(size_t)(m0 + ld_row) * 768 + k0 + cc]);
            CP_ASYNC16(sA[buf] + ld_row * PS + cc + 32, &g_X8[(size_t)(m0 + ld_row) * 768 + k0 + cc + 32]);
            CP_ASYNC16(sB[buf] + ld_row * PS + cc, &g_Wt8[(size_t)(n0 + ld_row) * 768 + k0 + cc]);
            CP_ASYNC16(sB[buf] + ld_row * PS + cc + 32, &g_Wt8[(size_t)(n0 + ld_row) * 768 + k0 + cc + 32]);
        }
        CP_COMMIT();
    };

    fill(0, 0);
    fill(1, 128);

    const int NT = 6;
    for (int kt = 0; kt < NT; kt++) {
        if (kt + 1 < NT) { CP_WAIT(1); } else { CP_WAIT(0); }
        __syncthreads();
        if (kt + 2 < NT) fill(kt & 1, (kt + 2) * 128);

        const uint32_t sa = sA[kt & 1], sb = sB[kt & 1];
        #pragma unroll
        for (int ks = 0; ks < 4; ks++) {
            uint32_t af[4][4];
            #pragma unroll
            for (int mi = 0; mi < 4; mi++)
                ldm_x4(af[mi], sa + (wm * 64 + mi * 16 + a_r) * PS + ks * 32 + a_c);
            uint32_t bf[4][2];
            #pragma unroll
            for (int np = 0; np < 2; np++) {
                uint32_t tmp[4];
                ldm_x4(tmp, sb + (wn * 32 + np * 16 + b_r) * PS + ks * 32 + b_c);
                bf[2 * np][0] = tmp[0]; bf[2 * np][1] = tmp[1];
                bf[2 * np + 1][0] = tmp[2]; bf[2 * np + 1][1] = tmp[3];
            }
            #pragma unroll
            for (int mi = 0; mi < 4; mi++)
                #pragma unroll
                for (int ni = 0; ni < 4; ni++)
                    mma_fp8(c[mi][ni], af[mi], bf[ni]);
        }
    }
    __syncthreads();

    uint8_t* stg = As[0];   // 128 x STG_S (cols 0..63 q, 64..127 k) = 24576B

    #pragma unroll
    for (int mi = 0; mi < 4; mi++) {
        #pragma unroll
        for (int ni = 0; ni < 4; ni++) {
            const int rloc = wm * 64 + mi * 16 + g;
            const int cloc = wn * 32 + ni * 8 + 2 * tg;
            const int n = n0 + cloc;
            const int fi = (cloc & 63) >> 1;
            const float inv = invf_s[fi];
            const float b0v = bias[n], b1v = bias[n + 1];
            const float x00 = c[mi][ni][0] * INV_W_SCALE + b0v;
            const float x01 = c[mi][ni][1] * INV_W_SCALE + b1v;
            const float x10 = c[mi][ni][2] * INV_W_SCALE + b0v;
            const float x11 = c[mi][ni][3] * INV_W_SCALE + b1v;
            const int s0 = (m0 + rloc) & 511;
            float sn0, cs0, sn1, cs1;
            __sincosf((float)s0 * inv, &sn0, &cs0);
            __sincosf((float)(s0 + 8) * inv, &sn1, &cs1);
            const float y00 = x00 * cs0 - x01 * sn0, y01 = x01 * cs0 + x00 * sn0;
            const float y10 = x10 * cs1 - x11 * sn1, y11 = x11 * cs1 + x10 * sn1;
            *(uint16_t*)&stg[rloc * STG_S + cloc]       = pack_e4m3x2(y01, y00);
            *(uint16_t*)&stg[(rloc + 8) * STG_S + cloc] = pack_e4m3x2(y11, y10);
        }
    }
    __syncthreads();

    const int ent = n0 >> 7;
    #pragma unroll
    for (int j = 0; j < 4; j++) {
        const int idx = j * 256 + t;
        const int isK = idx >> 9;
        const int rc = idx & 511;
        const int row = rc >> 2, c16 = (rc & 3) * 16;
        const int m = m0 + row, bb = m >> 9, s = m & 511;
        uint4 v = *(uint4*)&stg[row * STG_S + isK * 64 + c16];
        uint8_t* p = isK ? g_k8 : g_q8;
        *(uint4*)&p[(((size_t)(bb * 9 + ent)) * 512 + s) * 64 + c16] = v;
    }
}

// ---------------- Kernel B: QK^T (fp8), persistent m-tile, pipelined n-loop ----------------
__global__ __launch_bounds__(256, 3) void attn_mma_kernel(const float* __restrict__ amask,
                                                          float* __restrict__ out)
{
    const int S = 80;
    __shared__ __align__(16) uint8_t Qs[64 * 80];
    __shared__ __align__(16) uint8_t Ks[2][128 * 80];

    const int t = threadIdx.x, lane = t & 31, wid = t >> 5;
    const int wm = wid >> 2, wn = wid & 3;
    const int g = lane >> 2, tg = lane & 3;
    const int qd = lane >> 3, rr8 = lane & 7;
    const int a_r = (qd & 1) * 8 + rr8, a_c = (qd >> 1) * 16;
    const int b_r = (qd >> 1) * 8 + rr8, b_c = (qd & 1) * 16;

    const int tm = blockIdx.x, bh = blockIdx.y;
    const int b = bh / 9;
    const int m0 = tm * 64;
    const int tn_start = tm >> 1;

    const size_t qbase = (size_t)bh * 512 * 64;

    const uint32_t sK0 = smem_u32(Ks[0]), sK1 = smem_u32(Ks[1]);
    auto fillK = [&](int buf, int n0) {
        const uint32_t sk = buf ? sK1 : sK0;
        #pragma unroll
        for (int p = 0; p < 2; p++) {
            const int idx = p * 256 + t;
            const int row = idx >> 2, cc = (idx & 3) * 16;
            CP_ASYNC16(sk + row * S + cc, &g_k8[qbase + (size_t)(n0 + row) * 64 + cc]);
        }
        CP_COMMIT();
    };
    fillK(0, tn_start * 128);

    {
        const int row = t >> 2, cc = (t & 3) * 16;
        *(uint4*)&Qs[row * S + cc] = *(const uint4*)&g_q8[qbase + (size_t)(m0 + row) * 64 + cc];
    }

    for (int tn = 0; tn < tn_start; tn++) {
        const int n0 = tn * 128;
        const int cg = (t & 31) * 4, rbase = t >> 5;
        float4 v;
        #pragma unroll
        for (int ci = 0; ci < 4; ci++) {
            float pad = amask[b * 512 + n0 + cg + ci];
            ((float*)&v)[ci] = (-(1.0f - pad) * NEG_INF_F - NEG_INF_F) * 0.125f;
        }
        #pragma unroll
        for (int rp = 0; rp < 8; rp++) {
            int m = m0 + rbase + rp * 8;
            *(float4*)&out[((size_t)bh * 512 + m) * 512 + n0 + cg] = v;
        }
    }

    const uint32_t sQ = smem_u32(Qs);
    int buf = 0;
    for (int tn = tn_start; tn < 4; tn++) {
        const int n0 = tn * 128;
        CP_WAIT(0);
        __syncthreads();
        if (tn + 1 < 4) fillK(buf ^ 1, (tn + 1) * 128);

        const uint32_t sk = buf ? sK1 : sK0;
        float c[2][4][4];
        #pragma unroll
        for (int i = 0; i < 2; i++)
            #pragma unroll
            for (int j = 0; j < 4; j++)
                #pragma unroll
                for (int k = 0; k < 4; k++) c[i][j][k] = 0.f;

        #pragma unroll
        for (int ks = 0; ks < 2; ks++) {
            uint32_t af[2][4];
            #pragma unroll
            for (int mi = 0; mi < 2; mi++)
                ldm_x4(af[mi], sQ + (wm * 32 + mi * 16 + a_r) * S + ks * 32 + a_c);
            uint32_t bf[4][2];
            #pragma unroll
            for (int np = 0; np < 2; np++) {
                uint32_t tmp[4];
                ldm_x4(tmp, sk + (wn * 32 + np * 16 + b_r) * S + ks * 32 + b_c);
                bf[2 * np][0] = tmp[0]; bf[2 * np][1] = tmp[1];
                bf[2 * np + 1][0] = tmp[2]; bf[2 * np + 1][1] = tmp[3];
            }
            #pragma unroll
            for (int mi = 0; mi < 2; mi++)
                #pragma unroll
                for (int ni = 0; ni < 4; ni++)
                    mma_fp8(c[mi][ni], af[mi], bf[ni]);
        }

        #pragma unroll
        for (int mi = 0; mi < 2; mi++) {
            #pragma unroll
            for (int ni = 0; ni < 4; ni++) {
                const int row0 = m0 + wm * 32 + mi * 16 + g;
                const int row1 = row0 + 8;
                const int n = n0 + wn * 32 + ni * 8 + 2 * tg;
                const float pad0 = amask[b * 512 + n];
                const float pad1 = amask[b * 512 + n + 1];
                const float* cc = c[mi][ni];
                float v00 = cc[0] * pad0 - (1.f - pad0) * NEG_INF_F - (n     < row0 ? NEG_INF_F : 0.f);
                float v01 = cc[1] * pad1 - (1.f - pad1) * NEG_INF_F - (n + 1 < row0 ? NEG_INF_F : 0.f);
                float v10 = cc[2] * pad0 - (1.f - pad0) * NEG_INF_F - (n     < row1 ? NEG_INF_F : 0.f);
                float v11 = cc[3] * pad1 - (1.f - pad1) * NEG_INF_F - (n + 1 < row1 ? NEG_INF_F : 0.f);
                float2 o0 = {v00 * 0.125f, v01 * 0.125f};
                float2 o1 = {v10 * 0.125f, v11 * 0.125f};
                *(float2*)&out[((size_t)bh * 512 + row0) * 512 + n] = o0;
                *(float2*)&out[((size_t)bh * 512 + row1) * 512 + n] = o1;
            }
        }
        buf ^= 1;
    }
}

// ---------------- launch ----------------
extern "C" void kernel_launch(void* const* d_in, const int* in_sizes, int n_in,
                              void* d_out, int out_size)
{
    const float* X    = (const float*)d_in[0];
    const float* amsk = (const float*)d_in[1];
    const float* W    = (const float*)d_in[2];
    const float* bias = (const float*)d_in[3];
    float* out = (float*)d_out;
    (void)in_sizes; (void)n_in; (void)out_size;

    conv_fused_kernel<<<1888, 256>>>(X, W);
    {
        dim3 grid(9, 64);
        proj_mma_kernel<<<grid, 256>>>(bias);
    }
    {
        dim3 grid(8, 144);
        attn_mma_kernel<<<grid, 256>>>(amsk, out);
    }
}

// round 14
// speedup vs baseline: 1.0951x; 1.0951x over previous
#include <cuda_runtime.h>
#include <cuda_bf16.h>
#include <cstdint>

#define NEG_INF_F 1000000000000.0f
#define W_SCALE 16.0f
#define INV_W_SCALE 0.0625f

// ---------------- scratch (fp8 e4m3) ----------------
__device__ uint8_t g_X8[8192 * 768];    // X e4m3 [m][k]
__device__ uint8_t g_Wt8[1152 * 768];   // (16*W)^T e4m3 [n][k]
__device__ uint8_t g_q8[144 * 512 * 64];
__device__ uint8_t g_k8[144 * 512 * 64];

// ---------------- PTX helpers ----------------
__device__ __forceinline__ uint32_t smem_u32(const void* p) {
    return (uint32_t)__cvta_generic_to_shared(p);
}
__device__ __forceinline__ void ldm_x4(uint32_t* r, uint32_t a) {
    asm volatile("ldmatrix.sync.aligned.m8n8.x4.shared.b16 {%0,%1,%2,%3}, [%4];"
                 : "=r"(r[0]), "=r"(r[1]), "=r"(r[2]), "=r"(r[3]) : "r"(a));
}
__device__ __forceinline__ void mma_fp8(float* c, const uint32_t* a, const uint32_t* b) {
    asm volatile(
        "mma.sync.aligned.m16n8k32.row.col.f32.e4m3.e4m3.f32 "
        "{%0,%1,%2,%3}, {%4,%5,%6,%7}, {%8,%9}, {%0,%1,%2,%3};"
        : "+f"(c[0]), "+f"(c[1]), "+f"(c[2]), "+f"(c[3])
        : "r"(a[0]), "r"(a[1]), "r"(a[2]), "r"(a[3]), "r"(b[0]), "r"(b[1]));
}
__device__ __forceinline__ uint16_t pack_e4m3x2(float hi, float lo) {
    uint16_t r;
    asm("cvt.rn.satfinite.e4m3x2.f32 %0, %1, %2;" : "=h"(r) : "f"(hi), "f"(lo));
    return r;
}
#define CP_ASYNC16(dst, src) \
    asm volatile("cp.async.cg.shared.global [%0], [%1], 16;" :: "r"(dst), "l"(src))
#define CP_COMMIT() asm volatile("cp.async.commit_group;")
#define CP_WAIT(N)  asm volatile("cp.async.wait_group %0;" :: "n"(N))

// ---------------- fused convert kernel ----------------
// blocks [0, 864): W transpose+convert; blocks [864, ...): X convert (2 float4/iter).
__global__ __launch_bounds__(256) void conv_fused_kernel(const float* __restrict__ X,
                                                         const float* __restrict__ W)
{
    if (blockIdx.x < 864) {
        __shared__ float tile[32][33];
        const int bx = blockIdx.x % 36, by = blockIdx.x / 36;
        const int n0 = bx * 32, k0 = by * 32;
        const int tx = threadIdx.x & 31, ty = threadIdx.x >> 5;
        #pragma unroll
        for (int i = 0; i < 4; i++)
            tile[ty + 8 * i][tx] = W[(size_t)(k0 + ty + 8 * i) * 1152 + n0 + tx];
        __syncthreads();
        #pragma unroll
        for (int i = 0; i < 4; i++) {
            const int n = ty + 8 * i;
            float v = tile[tx][n] * W_SCALE;
            uint16_t p = pack_e4m3x2(0.0f, v);
            g_Wt8[(size_t)(n0 + n) * 768 + k0 + tx] = (uint8_t)(p & 0xFF);
        }
    } else {
        const int n4 = 8192 * 768 / 4;
        const int nb = gridDim.x - 864;
        const int stride = nb * 256;
        for (int i = (blockIdx.x - 864) * 256 + threadIdx.x; i < n4; i += 2 * stride) {
            float4 v0 = ((const float4*)X)[i];
            const int i2 = i + stride;
            float4 v1 = (i2 < n4) ? ((const float4*)X)[i2] : make_float4(0, 0, 0, 0);
            uint16_t lo0 = pack_e4m3x2(v0.y, v0.x), hi0 = pack_e4m3x2(v0.w, v0.z);
            ((uint32_t*)g_X8)[i] = ((uint32_t)hi0 << 16) | lo0;
            if (i2 < n4) {
                uint16_t lo1 = pack_e4m3x2(v1.y, v1.x), hi1 = pack_e4m3x2(v1.w, v1.z);
                ((uint32_t*)g_X8)[i2] = ((uint32_t)hi1 << 16) | lo1;
            }
        }
    }
}

// ---------------- Kernel A: proj GEMM (fp8) + bias + RoPE, staged fp8 output ----------------
// 128x128 tile, 8 warps (2m x 4n), warp tile 64x32, 64B K-tile, 3-stage pipeline.
#define STG_S 192

__global__ __launch_bounds__(256, 2) void proj_mma_kernel(const float* __restrict__ bias)
{
    const int S = 80;
    __shared__ __align__(16) uint8_t As[3][128 * 80];   // reused as output staging
    __shared__ __align__(16) uint8_t Bs[3][128 * 80];
    __shared__ float invf_s[32];
    __shared__ float bias_s[128];

    const int t = threadIdx.x, lane = t & 31, wid = t >> 5;
    const int wm = wid >> 2, wn = wid & 3;
    const int g = lane >> 2, tg = lane & 3;
    const int qd = lane >> 3, rr8 = lane & 7;
    const int m0 = blockIdx.y * 128, n0 = blockIdx.x * 128;

    const int a_r = (qd & 1) * 8 + rr8, a_c = (qd >> 1) * 16;
    const int b_r = (qd >> 1) * 8 + rr8, b_c = (qd & 1) * 16;

    if (t < 32) {
        invf_s[t] = exp2f((float)t * (-13.287712379549449f / 32.0f));
        *(float4*)&bias_s[t * 4] = *(const float4*)&bias[n0 + t * 4];
    }

    float c[4][4][4];
    #pragma unroll
    for (int i = 0; i < 4; i++)
        #pragma unroll
        for (int j = 0; j < 4; j++)
            #pragma unroll
            for (int k = 0; k < 4; k++) c[i][j][k] = 0.f;

    const uint32_t sA[3] = {smem_u32(As[0]), smem_u32(As[1]), smem_u32(As[2])};
    const uint32_t sB[3] = {smem_u32(Bs[0]), smem_u32(Bs[1]), smem_u32(Bs[2])};

    const int ld_row = t >> 2, ld_c = (t & 3) * 16;
    auto fill = [&](int buf, int k0) {
        CP_ASYNC16(sA[buf] + ld_row * S + ld_c, &g_X8[(size_t)(m0 + ld_row) * 768 + k0 + ld_c]);
        CP_ASYNC16(sB[buf] + ld_row * S + ld_c, &g_Wt8[(size_t)(n0 + ld_row) * 768 + k0 + ld_c]);
        const int row2 = ld_row + 64;
        CP_ASYNC16(sA[buf] + row2 * S + ld_c, &g_X8[(size_t)(m0 + row2) * 768 + k0 + ld_c]);
        CP_ASYNC16(sB[buf] + row2 * S + ld_c, &g_Wt8[(size_t)(n0 + row2) * 768 + k0 + ld_c]);
        CP_COMMIT();
    };

    fill(0, 0);
    fill(1, 64);

    const int NT = 12;
    for (int kt = 0; kt < NT; kt++) {
        if (kt + 1 < NT) { CP_WAIT(1); } else { CP_WAIT(0); }
        __syncthreads();
        if (kt + 2 < NT) fill((kt + 2) % 3, (kt + 2) * 64);

        const uint32_t sa = sA[kt % 3], sb = sB[kt % 3];
        #pragma unroll
        for (int ks = 0; ks < 2; ks++) {
            uint32_t af[4][4];
            #pragma unroll
            for (int mi = 0; mi < 4; mi++)
                ldm_x4(af[mi], sa + (wm * 64 + mi * 16 + a_r) * S + ks * 32 + a_c);
            uint32_t bf[4][2];
            #pragma unroll
            for (int np = 0; np < 2; np++) {
                uint32_t tmp[4];
                ldm_x4(tmp, sb + (wn * 32 + np * 16 + b_r) * S + ks * 32 + b_c);
                bf[2 * np][0] = tmp[0]; bf[2 * np][1] = tmp[1];
                bf[2 * np + 1][0] = tmp[2]; bf[2 * np + 1][1] = tmp[3];
            }
            #pragma unroll
            for (int mi = 0; mi < 4; mi++)
                #pragma unroll
                for (int ni = 0; ni < 4; ni++)
                    mma_fp8(c[mi][ni], af[mi], bf[ni]);
        }
    }
    __syncthreads();

    uint8_t* stg = As[0];   // 128 x STG_S (cols 0..63 q, 64..127 k)

    #pragma unroll
    for (int mi = 0; mi < 4; mi++) {
        #pragma unroll
        for (int ni = 0; ni < 4; ni++) {
            const int rloc = wm * 64 + mi * 16 + g;
            const int cloc = wn * 32 + ni * 8 + 2 * tg;
            const int fi = (cloc & 63) >> 1;
            const float inv = invf_s[fi];
            const float b0v = bias_s[cloc], b1v = bias_s[cloc + 1];
            const float x00 = c[mi][ni][0] * INV_W_SCALE + b0v;
            const float x01 = c[mi][ni][1] * INV_W_SCALE + b1v;
            const float x10 = c[mi][ni][2] * INV_W_SCALE + b0v;
            const float x11 = c[mi][ni][3] * INV_W_SCALE + b1v;
            const int s0 = (m0 + rloc) & 511;
            float sn0, cs0, sn1, cs1;
            __sincosf((float)s0 * inv, &sn0, &cs0);
            __sincosf((float)(s0 + 8) * inv, &sn1, &cs1);
            const float y00 = x00 * cs0 - x01 * sn0, y01 = x01 * cs0 + x00 * sn0;
            const float y10 = x10 * cs1 - x11 * sn1, y11 = x11 * cs1 + x10 * sn1;
            *(uint16_t*)&stg[rloc * STG_S + cloc]       = pack_e4m3x2(y01, y00);
            *(uint16_t*)&stg[(rloc + 8) * STG_S + cloc] = pack_e4m3x2(y11, y10);
        }
    }
    __syncthreads();

    const int ent = n0 >> 7;
    #pragma unroll
    for (int j = 0; j < 4; j++) {
        const int idx = j * 256 + t;
        const int isK = idx >> 9;
        const int rc = idx & 511;
        const int row = rc >> 2, c16 = (rc & 3) * 16;
        const int m = m0 + row, bb = m >> 9, s = m & 511;
        uint4 v = *(uint4*)&stg[row * STG_S + isK * 64 + c16];
        uint8_t* p = isK ? g_k8 : g_q8;
        *(uint4*)&p[(((size_t)(bb * 9 + ent)) * 512 + s) * 64 + c16] = v;
    }
}

// ---------------- Kernel B: QK^T (fp8), persistent m-tile, pipelined n-loop ----------------
__global__ __launch_bounds__(256, 3) void attn_mma_kernel(const float* __restrict__ amask,
                                                          float* __restrict__ out)
{
    const int S = 80;
    __shared__ __align__(16) uint8_t Qs[64 * 80];
    __shared__ __align__(16) uint8_t Ks[2][128 * 80];

    const int t = threadIdx.x, lane = t & 31, wid = t >> 5;
    const int wm = wid >> 2, wn = wid & 3;
    const int g = lane >> 2, tg = lane & 3;
    const int qd = lane >> 3, rr8 = lane & 7;
    const int a_r = (qd & 1) * 8 + rr8, a_c = (qd >> 1) * 16;
    const int b_r = (qd >> 1) * 8 + rr8, b_c = (qd & 1) * 16;

    const int tm = blockIdx.x, bh = blockIdx.y;
    const int b = bh / 9;
    const int m0 = tm * 64;
    const int tn_start = tm >> 1;

    const size_t qbase = (size_t)bh * 512 * 64;

    const uint32_t sK0 = smem_u32(Ks[0]), sK1 = smem_u32(Ks[1]);
    auto fillK = [&](int buf, int n0) {
        const uint32_t sk = buf ? sK1 : sK0;
        #pragma unroll
        for (int p = 0; p < 2; p++) {
            const int idx = p * 256 + t;
            const int row = idx >> 2, cc = (idx & 3) * 16;
            CP_ASYNC16(sk + row * S + cc, &g_k8[qbase + (size_t)(n0 + row) * 64 + cc]);
        }
        CP_COMMIT();
    };
    fillK(0, tn_start * 128);

    {
        const int row = t >> 2, cc = (t & 3) * 16;
        *(uint4*)&Qs[row * S + cc] = *(const uint4*)&g_q8[qbase + (size_t)(m0 + row) * 64 + cc];
    }

    for (int tn = 0; tn < tn_start; tn++) {
        const int n0 = tn * 128;
        const int cg = (t & 31) * 4, rbase = t >> 5;
        float4 v;
        #pragma unroll
        for (int ci = 0; ci < 4; ci++) {
            float pad = amask[b * 512 + n0 + cg + ci];
            ((float*)&v)[ci] = (-(1.0f - pad) * NEG_INF_F - NEG_INF_F) * 0.125f;
        }
        #pragma unroll
        for (int rp = 0; rp < 8; rp++) {
            int m = m0 + rbase + rp * 8;
            *(float4*)&out[((size_t)bh * 512 + m) * 512 + n0 + cg] = v;
        }
    }

    const uint32_t sQ = smem_u32(Qs);
    int buf = 0;
    for (int tn = tn_start; tn < 4; tn++) {
        const int n0 = tn * 128;
        CP_WAIT(0);
        __syncthreads();
        if (tn + 1 < 4) fillK(buf ^ 1, (tn + 1) * 128);

        const uint32_t sk = buf ? sK1 : sK0;
        float c[2][4][4];
        #pragma unroll
        for (int i = 0; i < 2; i++)
            #pragma unroll
            for (int j = 0; j < 4; j++)
                #pragma unroll
                for (int k = 0; k < 4; k++) c[i][j][k] = 0.f;

        #pragma unroll
        for (int ks = 0; ks < 2; ks++) {
            uint32_t af[2][4];
            #pragma unroll
            for (int mi = 0; mi < 2; mi++)
                ldm_x4(af[mi], sQ + (wm * 32 + mi * 16 + a_r) * S + ks * 32 + a_c);
            uint32_t bf[4][2];
            #pragma unroll
            for (int np = 0; np < 2; np++) {
                uint32_t tmp[4];
                ldm_x4(tmp, sk + (wn * 32 + np * 16 + b_r) * S + ks * 32 + b_c);
                bf[2 * np][0] = tmp[0]; bf[2 * np][1] = tmp[1];
                bf[2 * np + 1][0] = tmp[2]; bf[2 * np + 1][1] = tmp[3];
            }
            #pragma unroll
            for (int mi = 0; mi < 2; mi++)
                #pragma unroll
                for (int ni = 0; ni < 4; ni++)
                    mma_fp8(c[mi][ni], af[mi], bf[ni]);
        }

        #pragma unroll
        for (int mi = 0; mi < 2; mi++) {
            #pragma unroll
            for (int ni = 0; ni < 4; ni++) {
                const int row0 = m0 + wm * 32 + mi * 16 + g;
                const int row1 = row0 + 8;
                const int n = n0 + wn * 32 + ni * 8 + 2 * tg;
                const float pad0 = amask[b * 512 + n];
                const float pad1 = amask[b * 512 + n + 1];
                const float* cc = c[mi][ni];
                float v00 = cc[0] * pad0 - (1.f - pad0) * NEG_INF_F - (n     < row0 ? NEG_INF_F : 0.f);
                float v01 = cc[1] * pad1 - (1.f - pad1) * NEG_INF_F - (n + 1 < row0 ? NEG_INF_F : 0.f);
                float v10 = cc[2] * pad0 - (1.f - pad0) * NEG_INF_F - (n     < row1 ? NEG_INF_F : 0.f);
                float v11 = cc[3] * pad1 - (1.f - pad1) * NEG_INF_F - (n + 1 < row1 ? NEG_INF_F : 0.f);
                float2 o0 = {v00 * 0.125f, v01 * 0.125f};
                float2 o1 = {v10 * 0.125f, v11 * 0.125f};
                *(float2*)&out[((size_t)bh * 512 + row0) * 512 + n] = o0;
                *(float2*)&out[((size_t)bh * 512 + row1) * 512 + n] = o1;
            }
        }
        buf ^= 1;
    }
}

// ---------------- launch ----------------
extern "C" void kernel_launch(void* const* d_in, const int* in_sizes, int n_in,
                              void* d_out, int out_size)
{
    const float* X    = (const float*)d_in[0];
    const float* amsk = (const float*)d_in[1];
    const float* W    = (const float*)d_in[2];
    const float* bias = (const float*)d_in[3];
    float* out = (float*)d_out;
    (void)in_sizes; (void)n_in; (void)out_size;

    conv_fused_kernel<<<1888, 256>>>(X, W);
    {
        dim3 grid(9, 64);
        proj_mma_kernel<<<grid, 256>>>(bias);
    }
    {
        dim3 grid(8, 144);
        attn_mma_kernel<<<grid, 256>>>(amsk, out);
    }
}